// round 11
// baseline (speedup 1.0000x reference)
#include <cuda_runtime.h>

// Problem constants
#define T_STEPS 256
#define I1 38
#define H1 50
#define H2 15
#define NC 14
#define K1 (I1 + H1)    // 88 = 4 x 22
#define KQL 22          // k per quarter
#define K2 (H1 + H2)    // 65
#define BT 28           // batches per block; grid 147 -> 1 block/SM
#define BTOT 4096
#define AST 28          // activation row stride (floats); 112B rows (16B-mult)
#define NTHREADS 576
#define NBLOCKS 147

// Shared layout (floats):
//  W1s [K1][H1][4]  17600   (k, unit, gate i/f/g/o)
//  W2s [K2][H2][4]   3900
//  b1v [H1][4]        200
//  b2v [H2][4]         60
//  wfcs[NC*H2]        210
//  bfcs[NC]            14
//  a1  [2][K1][AST]  4928   rows 0..I1-1 = x_t, rows I1.. = h1
//  a2  [2][H2][AST]   840   h2 only
#define OFF_W1   0
#define OFF_W2   (OFF_W1 + K1 * H1 * 4)
#define OFF_B1   (OFF_W2 + K2 * H2 * 4)
#define OFF_B2   (OFF_B1 + H1 * 4)
#define OFF_WFC  (OFF_B2 + H2 * 4)
#define OFF_BFC  (OFF_WFC + NC * H2)
#define OFF_A1   (OFF_BFC + NC + 2)      // +2 keeps 16B alignment (21984+2? no)
#undef OFF_A1
#define OFF_A1   (OFF_BFC + NC)          // 21984 floats -> 16B aligned
#define OFF_A2   (OFF_A1 + 2 * K1 * AST)
#define SMEM_FLOATS (OFF_A2 + 2 * H2 * AST)
#define SMEM_BYTES (SMEM_FLOATS * 4)     // ~111 KB; 1 block/SM

__device__ __forceinline__ float fsig(float x) {
    return __fdividef(1.0f, 1.0f + __expf(-x));
}
__device__ __forceinline__ float ftanh_fast(float x) {
    return 1.0f - __fdividef(2.0f, 1.0f + __expf(2.0f * x));
}

__device__ __forceinline__ unsigned long long pack2(float w) {
    unsigned long long r;
    asm("mov.b64 %0, {%1, %1};" : "=l"(r) : "f"(w));
    return r;
}
__device__ __forceinline__ unsigned long long packf2(float a, float b) {
    unsigned long long r;
    asm("mov.b64 %0, {%1, %2};" : "=l"(r) : "f"(a), "f"(b));
    return r;
}
__device__ __forceinline__ void ffma2(unsigned long long& d,
                                      unsigned long long a, unsigned long long b) {
    asm("fma.rn.f32x2 %0, %1, %2, %0;" : "+l"(d) : "l"(a), "l"(b));
}
__device__ __forceinline__ unsigned long long fadd2(unsigned long long a,
                                                    unsigned long long b) {
    unsigned long long r;
    asm("add.rn.f32x2 %0, %1, %2;" : "=l"(r) : "l"(a), "l"(b));
    return r;
}
__device__ __forceinline__ float2 unpk2(unsigned long long v) {
    float2 r;
    asm("mov.b64 {%0, %1}, %2;" : "=f"(r.x), "=f"(r.y) : "l"(v));
    return r;
}

extern __shared__ float smem[];

__global__ __launch_bounds__(NTHREADS, 1)
void lstm2_fused_kernel(const float* __restrict__ x,
                        const float* __restrict__ w_ih1, const float* __restrict__ w_hh1,
                        const float* __restrict__ b_ih1, const float* __restrict__ b_hh1,
                        const float* __restrict__ w_ih2, const float* __restrict__ w_hh2,
                        const float* __restrict__ b_ih2, const float* __restrict__ b_hh2,
                        const float* __restrict__ w_fc, const float* __restrict__ b_fc,
                        float* __restrict__ out)
{
    float* W1s  = smem + OFF_W1;
    float* W2s  = smem + OFF_W2;
    float* b1v  = smem + OFF_B1;
    float* b2v  = smem + OFF_B2;
    float* wfcs = smem + OFF_WFC;
    float* bfcs = smem + OFF_BFC;
    float* a1   = smem + OFF_A1;
    float* a2   = smem + OFF_A2;

    const int tid = threadIdx.x;
    const int b0  = blockIdx.x * BT;

    // ---- stage weights: (k, unit, gate) float4 ----
    for (int i = tid; i < K1 * H1 * 4; i += NTHREADS) {
        int k = i / (H1 * 4);
        int r = i - k * (H1 * 4);
        int uu = r >> 2, gi = r & 3;
        W1s[i] = (k < I1) ? w_ih1[(gi * H1 + uu) * I1 + k]
                          : w_hh1[(gi * H1 + uu) * H1 + (k - I1)];
    }
    for (int i = tid; i < K2 * H2 * 4; i += NTHREADS) {
        int k = i / (H2 * 4);
        int r = i - k * (H2 * 4);
        int uu = r >> 2, gi = r & 3;
        W2s[i] = (k < H1) ? w_ih2[(gi * H2 + uu) * H1 + k]
                          : w_hh2[(gi * H2 + uu) * H2 + (k - H1)];
    }
    for (int i = tid; i < H1 * 4; i += NTHREADS) {
        int uu = i >> 2, gi = i & 3;
        b1v[i] = b_ih1[gi * H1 + uu] + b_hh1[gi * H1 + uu];
    }
    for (int i = tid; i < H2 * 4; i += NTHREADS) {
        int uu = i >> 2, gi = i & 3;
        b2v[i] = b_ih2[gi * H2 + uu] + b_hh2[gi * H2 + uu];
    }
    for (int i = tid; i < NC * H2; i += NTHREADS) wfcs[i] = w_fc[i];
    for (int i = tid; i < NC; i += NTHREADS) bfcs[i] = b_fc[i];

    // ---- zero initial states (buffer 0); load x_0 (batch-clamped) ----
    for (int i = tid; i < H1 * AST; i += NTHREADS) a1[I1 * AST + i] = 0.0f;
    for (int i = tid; i < H2 * AST; i += NTHREADS) a2[i] = 0.0f;
    for (int i = tid; i < BT * I1; i += NTHREADS) {
        int b = i / I1, k = i % I1;
        int bg = b0 + b; if (bg > BTOT - 1) bg = BTOT - 1;
        a1[k * AST + b] = x[(size_t)bg * (T_STEPS * I1) + k];
    }

    // ---- thread roles ----
    // Phase 1: tids 0..399: u = tid>>3 (0..49), bh = (tid>>2)&1 (batch half of 14),
    //          kq = tid&3 (k quarter of 22). Groups of 4 kq-lanes merge partials.
    const bool is_p1 = (tid < 400);
    const int u  = tid >> 3;
    const int bh = (tid >> 2) & 1;
    const int kq = tid & 3;
    const bool evenk = ((kq & 1) == 0);
    const bool lowq  = (kq < 2);
    const unsigned p1mask = __ballot_sync(0xffffffffu, is_p1);

    // Phase 2: tids 416..520 (105): u2 = j/7, qd = j%7 (4 batches each)
    const bool is_p2 = (tid >= 416) && (tid < 521);
    const int j2 = tid - 416;
    const int u2 = j2 / 7;
    const int qd = j2 % 7;

    // Prefetch: tids 544..571: one batch per lane
    const bool is_pf = (tid >= 544) && (tid < 544 + BT);
    int bg_pf = 0;
    if (is_pf) { bg_pf = b0 + (tid - 544); if (bg_pf > BTOT - 1) bg_pf = BTOT - 1; }

    float c1r[4] = {0.f, 0.f, 0.f, 0.f};   // cell state for owned batch pairs
    float c2r[4] = {0.f, 0.f, 0.f, 0.f};

    __syncthreads();

    const ulonglong2* W1p = reinterpret_cast<const ulonglong2*>(W1s);
    const ulonglong2* W2p = reinterpret_cast<const ulonglong2*>(W2s);

    for (int t = 0; t < T_STEPS; ++t) {
        const int p = t & 1, q = p ^ 1;
        float* a1p = a1 + p * (K1 * AST);
        float* a1q = a1 + q * (K1 * AST);
        float* a2p = a2 + p * (H2 * AST);
        float* a2q = a2 + q * (H2 * AST);

        // ===== Phase 1: 400 threads; 4 gates x 7 batch-pairs, k-quarter each =====
        if (is_p1) {
            unsigned long long acc[4][7];
            {
                ulonglong2 bv = *reinterpret_cast<const ulonglong2*>(b1v + u * 4);
                float2 wif = unpk2(bv.x), wgo = unpk2(bv.y);
                unsigned long long B0 = (kq == 0) ? pack2(wif.x) : 0ull;
                unsigned long long B1 = (kq == 0) ? pack2(wif.y) : 0ull;
                unsigned long long B2 = (kq == 0) ? pack2(wgo.x) : 0ull;
                unsigned long long B3 = (kq == 0) ? pack2(wgo.y) : 0ull;
                #pragma unroll
                for (int j = 0; j < 7; ++j) {
                    acc[0][j] = B0; acc[1][j] = B1; acc[2][j] = B2; acc[3][j] = B3;
                }
            }
            const ulonglong2* wp = W1p + (KQL * kq) * H1 + u;
            const unsigned long long* ap =
                reinterpret_cast<const unsigned long long*>(a1p + (KQL * kq) * AST + 14 * bh);
            #pragma unroll 2
            for (int k = 0; k < KQL; ++k) {
                ulonglong2 wv = *wp; wp += H1;
                float2 wif = unpk2(wv.x), wgo = unpk2(wv.y);
                unsigned long long W0 = pack2(wif.x);
                unsigned long long W1 = pack2(wif.y);
                unsigned long long W2 = pack2(wgo.x);
                unsigned long long W3 = pack2(wgo.y);
                unsigned long long a0 = ap[0], a1v = ap[1], a2v = ap[2], a3v = ap[3];
                unsigned long long a4v = ap[4], a5v = ap[5], a6v = ap[6];
                ap += AST / 2;
                ffma2(acc[0][0], W0, a0); ffma2(acc[1][0], W1, a0);
                ffma2(acc[2][0], W2, a0); ffma2(acc[3][0], W3, a0);
                ffma2(acc[0][1], W0, a1v); ffma2(acc[1][1], W1, a1v);
                ffma2(acc[2][1], W2, a1v); ffma2(acc[3][1], W3, a1v);
                ffma2(acc[0][2], W0, a2v); ffma2(acc[1][2], W1, a2v);
                ffma2(acc[2][2], W2, a2v); ffma2(acc[3][2], W3, a2v);
                ffma2(acc[0][3], W0, a3v); ffma2(acc[1][3], W1, a3v);
                ffma2(acc[2][3], W2, a3v); ffma2(acc[3][3], W3, a3v);
                ffma2(acc[0][4], W0, a4v); ffma2(acc[1][4], W1, a4v);
                ffma2(acc[2][4], W2, a4v); ffma2(acc[3][4], W3, a4v);
                ffma2(acc[0][5], W0, a5v); ffma2(acc[1][5], W1, a5v);
                ffma2(acc[2][5], W2, a5v); ffma2(acc[3][5], W3, a5v);
                ffma2(acc[0][6], W0, a6v); ffma2(acc[1][6], W1, a6v);
                ffma2(acc[2][6], W2, a6v); ffma2(acc[3][6], W3, a6v);
            }

            // ---- merge round 1 (xor 1): even kq keeps bp0..3, odd keeps bp4..6 ----
            #pragma unroll
            for (int g = 0; g < 4; ++g) {
                #pragma unroll
                for (int j = 0; j < 4; ++j) {
                    const int js = (j < 3) ? j : 2;
                    unsigned long long sent = evenk ? acc[g][4 + js] : acc[g][j];
                    unsigned long long rcv = __shfl_xor_sync(p1mask, sent, 1);
                    if (evenk) acc[g][j] = fadd2(acc[g][j], rcv);
                    else if (j < 3) acc[g][4 + j] = fadd2(acc[g][4 + j], rcv);
                }
            }
            // ---- merge round 2 (xor 2): kq0->bp0,1 kq2->bp2,3 kq1->bp4,5 kq3->bp6 ----
            #pragma unroll
            for (int g = 0; g < 4; ++g) {
                #pragma unroll
                for (int j = 0; j < 2; ++j) {
                    unsigned long long sent =
                        evenk ? (lowq ? acc[g][2 + j] : acc[g][j])
                              : (lowq ? acc[g][6]     : acc[g][4 + j]);
                    unsigned long long rcv = __shfl_xor_sync(p1mask, sent, 2);
                    if (evenk) {
                        if (lowq) acc[g][j]     = fadd2(acc[g][j],     rcv);
                        else      acc[g][2 + j] = fadd2(acc[g][2 + j], rcv);
                    } else {
                        if (lowq) acc[g][4 + j] = fadd2(acc[g][4 + j], rcv);
                        else if (j == 0) acc[g][6] = fadd2(acc[g][6],  rcv);
                    }
                }
            }

            // ---- nonlinearity + store for owned pairs (constant indices only) ----
#define LSTM1_FIN(bp, slot) do {                                              \
    float2 vi = unpk2(acc[0][bp]);                                            \
    float2 vf = unpk2(acc[1][bp]);                                            \
    float2 vg = unpk2(acc[2][bp]);                                            \
    float2 vo = unpk2(acc[3][bp]);                                            \
    float h0, h1;                                                             \
    { float ig = fsig(vi.x), fg = fsig(vf.x);                                 \
      float gg = ftanh_fast(vg.x), og = fsig(vo.x);                           \
      float c = fg * c1r[2*(slot)] + ig * gg; c1r[2*(slot)] = c;              \
      h0 = og * ftanh_fast(c); }                                              \
    { float ig = fsig(vi.y), fg = fsig(vf.y);                                 \
      float gg = ftanh_fast(vg.y), og = fsig(vo.y);                           \
      float c = fg * c1r[2*(slot)+1] + ig * gg; c1r[2*(slot)+1] = c;          \
      h1 = og * ftanh_fast(c); }                                              \
    *reinterpret_cast<unsigned long long*>(                                   \
        a1q + (I1 + u) * AST + bh * 14 + 2 * (bp)) = packf2(h0, h1);          \
} while (0)

            if (kq == 0)      { LSTM1_FIN(0, 0); LSTM1_FIN(1, 1); }
            else if (kq == 1) { LSTM1_FIN(4, 0); LSTM1_FIN(5, 1); }
            else if (kq == 2) { LSTM1_FIN(2, 0); LSTM1_FIN(3, 1); }
            else              { LSTM1_FIN(6, 0); }
#undef LSTM1_FIN
        } else if (is_pf) {
            // prefetch x_{t+1}: one batch per lane, 38 consecutive floats
            if (t + 1 < T_STEPS) {
                const float* xr = x + (size_t)bg_pf * (T_STEPS * I1)
                                    + (size_t)(t + 1) * I1;
                float* dst = a1q + (tid - 544);
                #pragma unroll
                for (int k = 0; k < I1; ++k) dst[k * AST] = xr[k];
            }
        }

        __syncthreads();   // the ONLY barrier per step

        // ===== Phase 2: 105 threads; 1 unit x 4 gates x 4 batches =====
        if (is_p2) {
            ulonglong2 bv2 = *reinterpret_cast<const ulonglong2*>(b2v + u2 * 4);
            unsigned long long aif[4], ago[4];
            #pragma unroll
            for (int b = 0; b < 4; ++b) { aif[b] = bv2.x; ago[b] = bv2.y; }

            const ulonglong2* wp2 = W2p + u2;
            const float* ah = a1q + I1 * AST + 4 * qd;      // h1 (new)
            #pragma unroll 5
            for (int k = 0; k < H1; ++k) {
                ulonglong2 wv = *wp2; wp2 += H2;
                float4 af = *reinterpret_cast<const float4*>(ah); ah += AST;
                unsigned long long A0 = pack2(af.x);
                unsigned long long A1 = pack2(af.y);
                unsigned long long A2 = pack2(af.z);
                unsigned long long A3 = pack2(af.w);
                ffma2(aif[0], wv.x, A0); ffma2(ago[0], wv.y, A0);
                ffma2(aif[1], wv.x, A1); ffma2(ago[1], wv.y, A1);
                ffma2(aif[2], wv.x, A2); ffma2(ago[2], wv.y, A2);
                ffma2(aif[3], wv.x, A3); ffma2(ago[3], wv.y, A3);
            }
            const float* ah2 = a2p + 4 * qd;                // h2 (old)
            #pragma unroll
            for (int k = 0; k < H2; ++k) {
                ulonglong2 wv = *wp2; wp2 += H2;
                float4 af = *reinterpret_cast<const float4*>(ah2); ah2 += AST;
                unsigned long long A0 = pack2(af.x);
                unsigned long long A1 = pack2(af.y);
                unsigned long long A2 = pack2(af.z);
                unsigned long long A3 = pack2(af.w);
                ffma2(aif[0], wv.x, A0); ffma2(ago[0], wv.y, A0);
                ffma2(aif[1], wv.x, A1); ffma2(ago[1], wv.y, A1);
                ffma2(aif[2], wv.x, A2); ffma2(ago[2], wv.y, A2);
                ffma2(aif[3], wv.x, A3); ffma2(ago[3], wv.y, A3);
            }
            float hv[4];
            #pragma unroll
            for (int b = 0; b < 4; ++b) {
                float2 vif = unpk2(aif[b]);
                float2 vgo = unpk2(ago[b]);
                float ig = fsig(vif.x), fg = fsig(vif.y);
                float gg = ftanh_fast(vgo.x), og = fsig(vgo.y);
                float c = fg * c2r[b] + ig * gg; c2r[b] = c;
                hv[b] = og * ftanh_fast(c);
            }
            *reinterpret_cast<float4*>(a2q + u2 * AST + 4 * qd) =
                make_float4(hv[0], hv[1], hv[2], hv[3]);
        }
        // no barrier: next phase-1 touches disjoint rows/buffers
    }

    __syncthreads();
    // final h2 in buffer q of step 255: q = 0
    if (tid < BT * NC) {
        int b = tid / NC, n = tid % NC;
        int bg = b0 + b;
        if (bg < BTOT) {
            const float* h2f = a2;   // buffer 0
            float s = bfcs[n];
            #pragma unroll
            for (int j = 0; j < H2; ++j)
                s += h2f[j * AST + b] * wfcs[n * H2 + j];
            out[(size_t)bg * NC + n] = s;
        }
    }
}

extern "C" void kernel_launch(void* const* d_in, const int* in_sizes, int n_in,
                              void* d_out, int out_size)
{
    (void)in_sizes; (void)n_in; (void)out_size;
    const float* x     = (const float*)d_in[0];
    const float* w_ih1 = (const float*)d_in[1];
    const float* w_hh1 = (const float*)d_in[2];
    const float* b_ih1 = (const float*)d_in[3];
    const float* b_hh1 = (const float*)d_in[4];
    const float* w_ih2 = (const float*)d_in[5];
    const float* w_hh2 = (const float*)d_in[6];
    const float* b_ih2 = (const float*)d_in[7];
    const float* b_hh2 = (const float*)d_in[8];
    const float* w_fc  = (const float*)d_in[9];
    const float* b_fc  = (const float*)d_in[10];
    float* out = (float*)d_out;

    cudaFuncSetAttribute(lstm2_fused_kernel,
                         cudaFuncAttributeMaxDynamicSharedMemorySize, SMEM_BYTES);

    lstm2_fused_kernel<<<NBLOCKS, NTHREADS, SMEM_BYTES>>>(
        x, w_ih1, w_hh1, b_ih1, b_hh1,
        w_ih2, w_hh2, b_ih2, b_hh2,
        w_fc, b_fc, out);
}

// round 12
// speedup vs baseline: 1.2389x; 1.2389x over previous
#include <cuda_runtime.h>
#include <cuda_fp16.h>

// Problem constants
#define T_STEPS 256
#define I1 38
#define H1 50
#define H2 15
#define NC 14
#define K1 (I1 + H1)    // 88
#define K2 (H1 + H2)    // 65
#define BT 14           // batches per block (grid 296 = 2 x 148 SMs, balanced)
#define BTOT 4096
#define AST 20          // activation row stride (floats); 80B rows
#define NTHREADS 384
#define NBLOCKS 296

// Shared layout (bytes):
//  W1h [K1][H1][4] __half  35200
//  W2h [K2][H2][4] __half   7800
//  (pad to 16B)
//  b1v [H1][4] f32            800
//  b2v [H2][4] f32            240
//  wfcs[NC*H2] f32            840
//  bfcs[NC]    f32             56
//  a1  [2][K1][AST] f32     14080
//  a2  [2][H2][AST] f32      2400
#define OFFB_W1   0
#define OFFB_W2   (OFFB_W1 + K1 * H1 * 4 * 2)          // 35200
#define OFFB_B1   ((OFFB_W2 + K2 * H2 * 4 * 2 + 15) & ~15)  // 43008
#define OFFB_B2   (OFFB_B1 + H1 * 4 * 4)
#define OFFB_WFC  (OFFB_B2 + H2 * 4 * 4)
#define OFFB_BFC  (OFFB_WFC + NC * H2 * 4)
#define OFFB_A1   ((OFFB_BFC + NC * 4 + 15) & ~15)
#define OFFB_A2   (OFFB_A1 + 2 * K1 * AST * 4)
#define SMEM_BYTES (OFFB_A2 + 2 * H2 * AST * 4)        // ~61.4 KB

#define NPF (NTHREADS - 288)   // 96 prefetch threads
#define PFN ((BT * I1 + NPF - 1) / NPF)   // max slots per prefetch thread (6)

__device__ __forceinline__ float fsig(float x) {
    return __fdividef(1.0f, 1.0f + __expf(-x));
}
__device__ __forceinline__ float ftanh_fast(float x) {
    return 1.0f - __fdividef(2.0f, 1.0f + __expf(2.0f * x));
}

__device__ __forceinline__ unsigned long long pack2(float w) {
    unsigned long long r;
    asm("mov.b64 %0, {%1, %1};" : "=l"(r) : "f"(w));
    return r;
}
__device__ __forceinline__ void ffma2(unsigned long long& d,
                                      unsigned long long a, unsigned long long b) {
    asm("fma.rn.f32x2 %0, %1, %2, %0;" : "+l"(d) : "l"(a), "l"(b));
}
__device__ __forceinline__ float2 unpk2(unsigned long long v) {
    float2 r;
    asm("mov.b64 {%0, %1}, %2;" : "=f"(r.x), "=f"(r.y) : "l"(v));
    return r;
}

extern __shared__ char smemraw[];

__global__ __launch_bounds__(NTHREADS, 2)
void lstm2_fused_kernel(const float* __restrict__ x,
                        const float* __restrict__ w_ih1, const float* __restrict__ w_hh1,
                        const float* __restrict__ b_ih1, const float* __restrict__ b_hh1,
                        const float* __restrict__ w_ih2, const float* __restrict__ w_hh2,
                        const float* __restrict__ b_ih2, const float* __restrict__ b_hh2,
                        const float* __restrict__ w_fc, const float* __restrict__ b_fc,
                        float* __restrict__ out)
{
    __half* W1h = reinterpret_cast<__half*>(smemraw + OFFB_W1);
    __half* W2h = reinterpret_cast<__half*>(smemraw + OFFB_W2);
    float* b1v  = reinterpret_cast<float*>(smemraw + OFFB_B1);
    float* b2v  = reinterpret_cast<float*>(smemraw + OFFB_B2);
    float* wfcs = reinterpret_cast<float*>(smemraw + OFFB_WFC);
    float* bfcs = reinterpret_cast<float*>(smemraw + OFFB_BFC);
    float* a1   = reinterpret_cast<float*>(smemraw + OFFB_A1);
    float* a2   = reinterpret_cast<float*>(smemraw + OFFB_A2);

    const int tid = threadIdx.x;
    const int b0  = blockIdx.x * BT;

    // ---- stage weights (fp16): (k, unit, gate) groups ----
    for (int i = tid; i < K1 * H1 * 4; i += NTHREADS) {
        int k = i / (H1 * 4);
        int r = i - k * (H1 * 4);
        int uu = r >> 2, gi = r & 3;
        float v = (k < I1) ? w_ih1[(gi * H1 + uu) * I1 + k]
                           : w_hh1[(gi * H1 + uu) * H1 + (k - I1)];
        W1h[i] = __float2half(v);
    }
    for (int i = tid; i < K2 * H2 * 4; i += NTHREADS) {
        int k = i / (H2 * 4);
        int r = i - k * (H2 * 4);
        int uu = r >> 2, gi = r & 3;
        float v = (k < H1) ? w_ih2[(gi * H2 + uu) * H1 + k]
                           : w_hh2[(gi * H2 + uu) * H2 + (k - H1)];
        W2h[i] = __float2half(v);
    }
    for (int i = tid; i < H1 * 4; i += NTHREADS) {
        int uu = i >> 2, gi = i & 3;
        b1v[i] = b_ih1[gi * H1 + uu] + b_hh1[gi * H1 + uu];
    }
    for (int i = tid; i < H2 * 4; i += NTHREADS) {
        int uu = i >> 2, gi = i & 3;
        b2v[i] = b_ih2[gi * H2 + uu] + b_hh2[gi * H2 + uu];
    }
    for (int i = tid; i < NC * H2; i += NTHREADS) wfcs[i] = w_fc[i];
    for (int i = tid; i < NC; i += NTHREADS) bfcs[i] = b_fc[i];

    // ---- zero initial states (buffer 0); load x_0 (batch-clamped) ----
    for (int i = tid; i < H1 * AST; i += NTHREADS) a1[I1 * AST + i] = 0.0f;
    for (int i = tid; i < H2 * AST; i += NTHREADS) a2[i] = 0.0f;
    for (int i = tid; i < BT * I1; i += NTHREADS) {
        int b = i / I1, k = i % I1;
        int bg = b0 + b; if (bg > BTOT - 1) bg = BTOT - 1;
        a1[k * AST + b] = x[(size_t)bg * (T_STEPS * I1) + k];
    }

    // ---- thread roles (identical to the 1456us config) ----
    const bool is_p1 = (tid < 200);
    const int u    = tid >> 2;
    const int quad = tid & 3;       // 4 batch columns each

    const bool is_p2 = (tid >= 224) && (tid < 284);
    const int j2   = tid - 224;
    const int gp   = j2 & 1;        // 0: gates i,f ; 1: gates g,o
    const int rst  = j2 >> 1;
    const int u2   = rst % 15;
    const int oct2 = rst / 15;      // 8 batch columns each
    const unsigned p2mask = __ballot_sync(0xffffffffu, is_p2);

    // Prefetch: tids 288..383, precomputed slots
    int pf_sts[PFN];
    int pf_gm[PFN];
    int pf_n = 0;
    if (tid >= 288) {
        for (int j = 0; j < PFN; ++j) {
            int i = (tid - 288) + j * NPF;
            if (i < BT * I1) {
                int b = i / I1, k = i - b * I1;
                int bg = b0 + b; if (bg > BTOT - 1) bg = BTOT - 1;
                pf_sts[j] = k * AST + b;
                pf_gm[j]  = bg * (T_STEPS * I1) + k;
                pf_n = j + 1;
            }
        }
    }

    float c1r[4] = {0.f,0.f,0.f,0.f};
    float c2r[4] = {0.f,0.f,0.f,0.f};

    __syncthreads();

    for (int t = 0; t < T_STEPS; ++t) {
        const int p = t & 1, q = p ^ 1;
        float* a1p = a1 + p * (K1 * AST);
        float* a1q = a1 + q * (K1 * AST);
        float* a2p = a2 + p * (H2 * AST);
        float* a2q = a2 + q * (H2 * AST);

        // ===== Phase 1: layer-1, 200 dense threads, 1u x 4g x 4b each =====
        if (is_p1) {
            unsigned long long acc[4][2];
            {
                float4 bv = *reinterpret_cast<const float4*>(b1v + u * 4);
                acc[0][0] = acc[0][1] = pack2(bv.x);
                acc[1][0] = acc[1][1] = pack2(bv.y);
                acc[2][0] = acc[2][1] = pack2(bv.z);
                acc[3][0] = acc[3][1] = pack2(bv.w);
            }
            // fp16 weights: 8B per (k,u) = 4 gate halves -> LDS.64
            const uint2* wp = reinterpret_cast<const uint2*>(W1h) + u;
            const char* ap = reinterpret_cast<const char*>(a1p) + 16 * quad;
            #pragma unroll 8
            for (int k = 0; k < K1; ++k) {
                uint2 wr = *wp; wp += H1;
                ulonglong2 av = *reinterpret_cast<const ulonglong2*>(ap);
                ap += AST * 4;
                __half2 h01 = *reinterpret_cast<__half2*>(&wr.x);
                __half2 h23 = *reinterpret_cast<__half2*>(&wr.y);
                float2 f01 = __half22float2(h01);
                float2 f23 = __half22float2(h23);
                unsigned long long w0 = pack2(f01.x);
                unsigned long long w1 = pack2(f01.y);
                unsigned long long w2 = pack2(f23.x);
                unsigned long long w3 = pack2(f23.y);
                ffma2(acc[0][0], w0, av.x); ffma2(acc[0][1], w0, av.y);
                ffma2(acc[1][0], w1, av.x); ffma2(acc[1][1], w1, av.y);
                ffma2(acc[2][0], w2, av.x); ffma2(acc[2][1], w2, av.y);
                ffma2(acc[3][0], w3, av.x); ffma2(acc[3][1], w3, av.y);
            }
            float hv[4];
            #pragma unroll
            for (int bp = 0; bp < 2; ++bp) {
                float2 vi = unpk2(acc[0][bp]);
                float2 vf = unpk2(acc[1][bp]);
                float2 vg = unpk2(acc[2][bp]);
                float2 vo = unpk2(acc[3][bp]);
                #pragma unroll
                for (int l = 0; l < 2; ++l) {
                    int bj = 2 * bp + l;
                    float ig = fsig(l ? vi.y : vi.x);
                    float fg = fsig(l ? vf.y : vf.x);
                    float gg = ftanh_fast(l ? vg.y : vg.x);
                    float og = fsig(l ? vo.y : vo.x);
                    float c  = fg * c1r[bj] + ig * gg;
                    c1r[bj]  = c;
                    hv[bj]   = og * ftanh_fast(c);
                }
            }
            *reinterpret_cast<float4*>(a1q + (I1 + u) * AST + 4 * quad) =
                make_float4(hv[0], hv[1], hv[2], hv[3]);
        } else if (tid >= 288) {
            if (t + 1 < T_STEPS) {
                const int xoff = (t + 1) * I1;
                #pragma unroll
                for (int j = 0; j < PFN; ++j) {
                    if (j < pf_n) a1q[pf_sts[j]] = x[pf_gm[j] + xoff];
                }
            }
        }

        __syncthreads();   // the ONLY barrier per step

        // ===== Phase 2: layer-2, 60 threads (warps 7-8), 1u x 2g x 8b each =====
        if (is_p2) {
            unsigned long long P[4], Q[4];   // gp0: P=i,Q=f ; gp1: P=g,Q=o
            {
                float2 bb = *reinterpret_cast<const float2*>(b2v + u2 * 4 + gp * 2);
                unsigned long long bl = pack2(bb.x), bh = pack2(bb.y);
                #pragma unroll
                for (int bp = 0; bp < 4; ++bp) { P[bp] = bl; Q[bp] = bh; }
            }
            // fp16 gate-pair weights: 4B per (k,u2,gp) -> LDS.32
            const __half2* wp2 =
                reinterpret_cast<const __half2*>(W2h) + u2 * 2 + gp;
            const char* ah = reinterpret_cast<const char*>(a1q + I1 * AST) + 32 * oct2; // h1 new
            #pragma unroll 5
            for (int k = 0; k < H1; ++k) {
                float2 wv = __half22float2(*wp2); wp2 += H2 * 2;
                ulonglong2 aL = *reinterpret_cast<const ulonglong2*>(ah);
                ulonglong2 aH = *reinterpret_cast<const ulonglong2*>(ah + 16);
                ah += AST * 4;
                unsigned long long wl = pack2(wv.x), wh = pack2(wv.y);
                ffma2(P[0], wl, aL.x); ffma2(P[1], wl, aL.y);
                ffma2(P[2], wl, aH.x); ffma2(P[3], wl, aH.y);
                ffma2(Q[0], wh, aL.x); ffma2(Q[1], wh, aL.y);
                ffma2(Q[2], wh, aH.x); ffma2(Q[3], wh, aH.y);
            }
            const char* ah2 = reinterpret_cast<const char*>(a2p) + 32 * oct2;  // h2 old
            #pragma unroll
            for (int k = 0; k < H2; ++k) {
                float2 wv = __half22float2(*wp2); wp2 += H2 * 2;
                ulonglong2 aL = *reinterpret_cast<const ulonglong2*>(ah2);
                ulonglong2 aH = *reinterpret_cast<const ulonglong2*>(ah2 + 16);
                ah2 += AST * 4;
                unsigned long long wl = pack2(wv.x), wh = pack2(wv.y);
                ffma2(P[0], wl, aL.x); ffma2(P[1], wl, aL.y);
                ffma2(P[2], wl, aH.x); ffma2(P[3], wl, aH.y);
                ffma2(Q[0], wh, aL.x); ffma2(Q[1], wh, aL.y);
                ffma2(Q[2], wh, aH.x); ffma2(Q[3], wh, aH.y);
            }
            // lane-pair exchange: even lane (gp0) keeps batch-pairs 0,1; odd keeps 2,3
            const bool evn = (gp == 0);
            unsigned long long GI[2], GF[2], GG[2], GO[2];
            #pragma unroll
            for (int jj = 0; jj < 2; ++jj) {
                unsigned long long sP = evn ? P[2 + jj] : P[jj];
                unsigned long long sQ = evn ? Q[2 + jj] : Q[jj];
                unsigned long long rP = __shfl_xor_sync(p2mask, sP, 1);
                unsigned long long rQ = __shfl_xor_sync(p2mask, sQ, 1);
                GI[jj] = evn ? P[jj]     : rP;
                GF[jj] = evn ? Q[jj]     : rQ;
                GG[jj] = evn ? rP        : P[2 + jj];
                GO[jj] = evn ? rQ        : Q[2 + jj];
            }
            float hv[4];
            #pragma unroll
            for (int jj = 0; jj < 2; ++jj) {
                float2 vi = unpk2(GI[jj]);
                float2 vf = unpk2(GF[jj]);
                float2 vg = unpk2(GG[jj]);
                float2 vo = unpk2(GO[jj]);
                #pragma unroll
                for (int l = 0; l < 2; ++l) {
                    int bj = 2 * jj + l;
                    float ig = fsig(l ? vi.y : vi.x);
                    float fg = fsig(l ? vf.y : vf.x);
                    float gg = ftanh_fast(l ? vg.y : vg.x);
                    float og = fsig(l ? vo.y : vo.x);
                    float c  = fg * c2r[bj] + ig * gg;
                    c2r[bj]  = c;
                    hv[bj]   = og * ftanh_fast(c);
                }
            }
            float* d = a2q + u2 * AST + oct2 * 8 + gp * 4;
            *reinterpret_cast<float4*>(d) = make_float4(hv[0], hv[1], hv[2], hv[3]);
        }
        // no barrier: next phase-1 touches disjoint rows/buffers
    }

    __syncthreads();
    // final h2 in buffer q of step 255: q = 0
    if (tid < BT * NC) {
        int b = tid / NC, n = tid % NC;
        int bg = b0 + b;
        if (bg < BTOT) {
            const float* h2f = a2;   // buffer 0
            float s = bfcs[n];
            #pragma unroll
            for (int j = 0; j < H2; ++j)
                s += h2f[j * AST + b] * wfcs[n * H2 + j];
            out[(size_t)bg * NC + n] = s;
        }
    }
}

extern "C" void kernel_launch(void* const* d_in, const int* in_sizes, int n_in,
                              void* d_out, int out_size)
{
    (void)in_sizes; (void)n_in; (void)out_size;
    const float* x     = (const float*)d_in[0];
    const float* w_ih1 = (const float*)d_in[1];
    const float* w_hh1 = (const float*)d_in[2];
    const float* b_ih1 = (const float*)d_in[3];
    const float* b_hh1 = (const float*)d_in[4];
    const float* w_ih2 = (const float*)d_in[5];
    const float* w_hh2 = (const float*)d_in[6];
    const float* b_ih2 = (const float*)d_in[7];
    const float* b_hh2 = (const float*)d_in[8];
    const float* w_fc  = (const float*)d_in[9];
    const float* b_fc  = (const float*)d_in[10];
    float* out = (float*)d_out;

    cudaFuncSetAttribute(lstm2_fused_kernel,
                         cudaFuncAttributeMaxDynamicSharedMemorySize, SMEM_BYTES);

    lstm2_fused_kernel<<<NBLOCKS, NTHREADS, SMEM_BYTES>>>(
        x, w_ih1, w_hh1, b_ih1, b_hh1,
        w_ih2, w_hh2, b_ih2, b_hh2,
        w_fc, b_fc, out);
}